// round 1
// baseline (speedup 1.0000x reference)
#include <cuda_runtime.h>
#include <math.h>

// Problem constants
#define BB   16
#define SS   257
#define DD   1024
#define HH   16
#define DHH  64
#define FFD  4096
#define LLN  6
#define PPP  14
#define NPS  16          // patches per side
#define NP   256         // patches per image
#define KC   (3*14*14)   // 588 im2col K
#define MM   (BB*SS)     // 4112 rows
#define LNEPS 1e-5f

// ---------------- scratch (static device globals; no allocation allowed) ----
__device__ float g_col [BB*NP*KC];    // im2col
__device__ float g_feat[BB*NP*DD];    // patch features
__device__ float g_h   [MM*DD];       // LN output
__device__ float g_q   [MM*DD];
__device__ float g_k   [MM*DD];
__device__ float g_v   [MM*DD];
__device__ float g_ctx [MM*DD];
__device__ float g_att [(size_t)BB*HH*SS*SS];  // scores / attn probs
__device__ float g_ff  [(size_t)MM*FFD];       // MLP hidden

// ---------------- im2col ----------------------------------------------------
__global__ void k_im2col(const float* __restrict__ px) {
    int idx = blockIdx.x * blockDim.x + threadIdx.x;
    const int total = BB*NP*KC;
    if (idx >= total) return;
    int kc = idx % KC;  int bp = idx / KC;
    int p  = bp % NP;   int b  = bp / NP;
    int c  = kc / (PPP*PPP); int rem = kc % (PPP*PPP);
    int i  = rem / PPP, j = rem % PPP;
    int py = p / NPS,   pxi = p % NPS;
    int row = py*PPP + i, col = pxi*PPP + j;
    g_col[idx] = px[((size_t)(b*3 + c)*224 + row)*224 + col];
}

// ---------------- generic GEMM: C = A[M,K] * B[N,K]^T (+bias, act, +add) ----
#define TBM 64
#define TBN 64
#define TBK 16
// act: 0 = none, 1 = quickGELU
__global__ void k_gemm(const float* __restrict__ A, const float* __restrict__ B,
                       const float* __restrict__ bias, const float* __restrict__ add,
                       float* __restrict__ C, int M, int N, int K, int act) {
    __shared__ float As[TBK][TBM+4];
    __shared__ float Bs[TBK][TBN+4];
    int tid = threadIdx.x;          // 256 threads
    int tx = tid & 15, ty = tid >> 4;
    int bm = blockIdx.y * TBM, bn = blockIdx.x * TBN;
    int lr = tid >> 2;              // 0..63 row within tile
    int lc = (tid & 3) * 4;         // 0,4,8,12 k offset
    float acc[4][4] = {};

    for (int k0 = 0; k0 < K; k0 += TBK) {
        // A tile
        {
            int ar = bm + lr;
            if (ar < M && (k0 + lc + 3) < K) {
                float4 t = *reinterpret_cast<const float4*>(&A[(size_t)ar*K + k0 + lc]);
                As[lc+0][lr] = t.x; As[lc+1][lr] = t.y;
                As[lc+2][lr] = t.z; As[lc+3][lr] = t.w;
            } else {
                #pragma unroll
                for (int i = 0; i < 4; i++) {
                    int kk = k0 + lc + i;
                    As[lc+i][lr] = (ar < M && kk < K) ? A[(size_t)ar*K + kk] : 0.f;
                }
            }
        }
        // B tile
        {
            int br = bn + lr;
            if (br < N && (k0 + lc + 3) < K) {
                float4 t = *reinterpret_cast<const float4*>(&B[(size_t)br*K + k0 + lc]);
                Bs[lc+0][lr] = t.x; Bs[lc+1][lr] = t.y;
                Bs[lc+2][lr] = t.z; Bs[lc+3][lr] = t.w;
            } else {
                #pragma unroll
                for (int i = 0; i < 4; i++) {
                    int kk = k0 + lc + i;
                    Bs[lc+i][lr] = (br < N && kk < K) ? B[(size_t)br*K + kk] : 0.f;
                }
            }
        }
        __syncthreads();
        #pragma unroll
        for (int kk = 0; kk < TBK; kk++) {
            float a[4], b[4];
            #pragma unroll
            for (int i = 0; i < 4; i++) a[i] = As[kk][ty*4+i];
            #pragma unroll
            for (int j = 0; j < 4; j++) b[j] = Bs[kk][tx*4+j];
            #pragma unroll
            for (int i = 0; i < 4; i++)
                #pragma unroll
                for (int j = 0; j < 4; j++)
                    acc[i][j] += a[i] * b[j];
        }
        __syncthreads();
    }

    #pragma unroll
    for (int i = 0; i < 4; i++) {
        int r = bm + ty*4 + i;
        if (r >= M) continue;
        #pragma unroll
        for (int j = 0; j < 4; j++) {
            int c = bn + tx*4 + j;
            if (c >= N) continue;
            float v = acc[i][j];
            if (bias) v += bias[c];
            if (act == 1) v = v / (1.f + __expf(-1.702f * v));   // quickGELU
            if (add) v += add[(size_t)r*N + c];
            C[(size_t)r*N + c] = v;
        }
    }
}

// ---------------- assemble embeddings: x = [cls | feats] + pos --------------
__global__ void k_assemble(const float* __restrict__ cls,
                           const float* __restrict__ pos,
                           float* __restrict__ x) {
    int idx = blockIdx.x * blockDim.x + threadIdx.x;
    if (idx >= MM*DD) return;
    int d = idx % DD; int bs = idx / DD;
    int s = bs % SS;  int b = bs / SS;
    float v = (s == 0) ? cls[d] : g_feat[((size_t)(b*NP + s - 1))*DD + d];
    x[idx] = v + pos[(size_t)s*DD + d];
}

// ---------------- LayerNorm over D=1024 per row ------------------------------
__global__ void k_ln(const float* __restrict__ x, const float* __restrict__ w,
                     const float* __restrict__ b, float* __restrict__ out) {
    int row = blockIdx.x;
    const float* xr = x + (size_t)row*DD;
    __shared__ float red[256];
    int t = threadIdx.x;
    float s = 0.f;
    for (int i = t; i < DD; i += 256) s += xr[i];
    red[t] = s; __syncthreads();
    for (int st = 128; st > 0; st >>= 1) { if (t < st) red[t] += red[t+st]; __syncthreads(); }
    float mean = red[0] * (1.f/DD);
    __syncthreads();
    float vs = 0.f;
    for (int i = t; i < DD; i += 256) { float d = xr[i]-mean; vs += d*d; }
    red[t] = vs; __syncthreads();
    for (int st = 128; st > 0; st >>= 1) { if (t < st) red[t] += red[t+st]; __syncthreads(); }
    float rstd = rsqrtf(red[0] * (1.f/DD) + LNEPS);
    float* o = out + (size_t)row*DD;
    for (int i = t; i < DD; i += 256) o[i] = (xr[i]-mean)*rstd*w[i] + b[i];
}

// ---------------- attention scores: att[bh,q,k] = scale * q.k ---------------
__global__ void k_scores(const float* __restrict__ Q, const float* __restrict__ Kt) {
    int bh = blockIdx.z;
    int b = bh / HH, h = bh % HH;
    int q0 = blockIdx.y * 16, k0 = blockIdx.x * 16;
    __shared__ float Qs[16][DHH+1];
    __shared__ float Ks[16][DHH+1];
    int tid = threadIdx.y*16 + threadIdx.x;
    int lr = tid >> 4;            // 0..15
    int lc = (tid & 15) * 4;      // 0..60
    {
        int qr = q0 + lr;
        if (qr < SS) {
            float4 t = *reinterpret_cast<const float4*>(&Q[((size_t)(b*SS+qr))*DD + h*DHH + lc]);
            Qs[lr][lc]=t.x; Qs[lr][lc+1]=t.y; Qs[lr][lc+2]=t.z; Qs[lr][lc+3]=t.w;
        } else { Qs[lr][lc]=Qs[lr][lc+1]=Qs[lr][lc+2]=Qs[lr][lc+3]=0.f; }
        int kr = k0 + lr;
        if (kr < SS) {
            float4 t = *reinterpret_cast<const float4*>(&Kt[((size_t)(b*SS+kr))*DD + h*DHH + lc]);
            Ks[lr][lc]=t.x; Ks[lr][lc+1]=t.y; Ks[lr][lc+2]=t.z; Ks[lr][lc+3]=t.w;
        } else { Ks[lr][lc]=Ks[lr][lc+1]=Ks[lr][lc+2]=Ks[lr][lc+3]=0.f; }
    }
    __syncthreads();
    int q = q0 + threadIdx.y, k = k0 + threadIdx.x;
    if (q < SS && k < SS) {
        float acc = 0.f;
        #pragma unroll
        for (int d = 0; d < DHH; d++) acc += Qs[threadIdx.y][d] * Ks[threadIdx.x][d];
        g_att[((size_t)bh*SS + q)*SS + k] = acc * 0.125f;   // DH^-0.5
    }
}

// ---------------- softmax over 257, single pass (row fits in registers) -----
__global__ void k_softmax() {
    size_t row = blockIdx.x;
    float* p = g_att + row * (size_t)SS;
    int t = threadIdx.x;                 // 256 threads
    float a = p[t];
    float extra = (t == 0) ? p[256] : -1e30f;
    __shared__ float red[256];
    float m = fmaxf(a, extra);
    red[t] = m; __syncthreads();
    for (int st = 128; st > 0; st >>= 1) { if (t < st) red[t] = fmaxf(red[t], red[t+st]); __syncthreads(); }
    m = red[0];
    __syncthreads();
    float ea = __expf(a - m);
    float eb = (t == 0) ? __expf(extra - m) : 0.f;
    red[t] = ea + eb; __syncthreads();
    for (int st = 128; st > 0; st >>= 1) { if (t < st) red[t] += red[t+st]; __syncthreads(); }
    float inv = 1.f / red[0];
    p[t] = ea * inv;
    if (t == 0) p[256] = eb * inv;
}

// ---------------- ctx[b,q,h,:] = attn[bh,q,:] @ V[b,:,h,:] ------------------
__global__ void k_ctx(const float* __restrict__ V, float* __restrict__ Ctx) {
    int bh = blockIdx.y; int b = bh / HH, h = bh % HH;
    int q0 = blockIdx.x * 16;
    int tx = threadIdx.x, ty = threadIdx.y;
    int tid = ty*16 + tx;
    __shared__ float As[16][17];
    __shared__ float Vs[16][DHH];
    const float* att = g_att + (size_t)bh*SS*SS;
    float acc[4] = {0.f, 0.f, 0.f, 0.f};
    int vlr = tid >> 4, vlc = (tid & 15) * 4;
    for (int k0 = 0; k0 < SS; k0 += 16) {
        int q = q0 + ty, kk_ = k0 + tx;
        As[ty][tx] = (q < SS && kk_ < SS) ? att[(size_t)q*SS + kk_] : 0.f;
        int kv = k0 + vlr;
        if (kv < SS) {
            float4 t4 = *reinterpret_cast<const float4*>(&V[((size_t)(b*SS+kv))*DD + h*DHH + vlc]);
            Vs[vlr][vlc]=t4.x; Vs[vlr][vlc+1]=t4.y; Vs[vlr][vlc+2]=t4.z; Vs[vlr][vlc+3]=t4.w;
        } else {
            Vs[vlr][vlc]=Vs[vlr][vlc+1]=Vs[vlr][vlc+2]=Vs[vlr][vlc+3]=0.f;
        }
        __syncthreads();
        #pragma unroll
        for (int kk = 0; kk < 16; kk++) {
            float a = As[ty][kk];
            #pragma unroll
            for (int j = 0; j < 4; j++) acc[j] += a * Vs[kk][tx + 16*j];
        }
        __syncthreads();
    }
    int q = q0 + ty;
    if (q < SS) {
        size_t base = ((size_t)(b*SS+q))*DD + h*DHH;
        #pragma unroll
        for (int j = 0; j < 4; j++) Ctx[base + tx + 16*j] = acc[j];
    }
}

// ---------------- host orchestration ----------------------------------------
extern "C" void kernel_launch(void* const* d_in, const int* in_sizes, int n_in,
                              void* d_out, int out_size) {
    const float* pixel    = (const float*)d_in[0];
    const float* patch_w  = (const float*)d_in[1];
    const float* class_e  = (const float*)d_in[2];
    const float* pos_e    = (const float*)d_in[3];
    const float* ln1_w    = (const float*)d_in[4];
    const float* ln1_b    = (const float*)d_in[5];
    const float* q_w      = (const float*)d_in[6];
    const float* q_b      = (const float*)d_in[7];
    const float* k_w      = (const float*)d_in[8];
    const float* k_b      = (const float*)d_in[9];
    const float* v_w      = (const float*)d_in[10];
    const float* v_b      = (const float*)d_in[11];
    const float* o_w      = (const float*)d_in[12];
    const float* o_b      = (const float*)d_in[13];
    const float* ln2_w    = (const float*)d_in[14];
    const float* ln2_b    = (const float*)d_in[15];
    const float* fc1_w    = (const float*)d_in[16];
    const float* fc1_b    = (const float*)d_in[17];
    const float* fc2_w    = (const float*)d_in[18];
    const float* fc2_b    = (const float*)d_in[19];
    float* x = (float*)d_out;   // residual stream lives in d_out

    float *col, *feat, *h, *q, *k, *v, *ctx, *ff;
    cudaGetSymbolAddress((void**)&col,  g_col);
    cudaGetSymbolAddress((void**)&feat, g_feat);
    cudaGetSymbolAddress((void**)&h,    g_h);
    cudaGetSymbolAddress((void**)&q,    g_q);
    cudaGetSymbolAddress((void**)&k,    g_k);
    cudaGetSymbolAddress((void**)&v,    g_v);
    cudaGetSymbolAddress((void**)&ctx,  g_ctx);
    cudaGetSymbolAddress((void**)&ff,   g_ff);

    // --- embeddings ---
    k_im2col<<<(BB*NP*KC + 255)/256, 256>>>(pixel);
    k_gemm<<<dim3(DD/TBN, (BB*NP + TBM-1)/TBM), 256>>>(col, patch_w, nullptr, nullptr,
                                                       feat, BB*NP, DD, KC, 0);
    k_assemble<<<(MM*DD + 255)/256, 256>>>(class_e, pos_e, x);

    dim3 gD (DD/TBN,  (MM + TBM-1)/TBM);   // N=1024 GEMMs
    dim3 gFF(FFD/TBN, (MM + TBM-1)/TBM);   // N=4096 GEMM

    for (int l = 0; l < LLN; l++) {
        const float* qw = q_w + (size_t)l*DD*DD;  const float* qb = q_b + (size_t)l*DD;
        const float* kw = k_w + (size_t)l*DD*DD;  const float* kb = k_b + (size_t)l*DD;
        const float* vw = v_w + (size_t)l*DD*DD;  const float* vb = v_b + (size_t)l*DD;
        const float* ow = o_w + (size_t)l*DD*DD;  const float* ob = o_b + (size_t)l*DD;
        const float* f1w = fc1_w + (size_t)l*FFD*DD; const float* f1b = fc1_b + (size_t)l*FFD;
        const float* f2w = fc2_w + (size_t)l*DD*FFD; const float* f2b = fc2_b + (size_t)l*DD;

        // attention block
        k_ln<<<MM, 256>>>(x, ln1_w + (size_t)l*DD, ln1_b + (size_t)l*DD, h);
        k_gemm<<<gD, 256>>>(h, qw, qb, nullptr, q, MM, DD, DD, 0);
        k_gemm<<<gD, 256>>>(h, kw, kb, nullptr, k, MM, DD, DD, 0);
        k_gemm<<<gD, 256>>>(h, vw, vb, nullptr, v, MM, DD, DD, 0);
        k_scores<<<dim3(17, 17, BB*HH), dim3(16,16)>>>(q, k);
        k_softmax<<<BB*HH*SS, 256>>>();
        k_ctx<<<dim3(17, BB*HH), dim3(16,16)>>>(v, ctx);
        k_gemm<<<gD, 256>>>(ctx, ow, ob, x, x, MM, DD, DD, 0);   // +residual

        // MLP block
        k_ln<<<MM, 256>>>(x, ln2_w + (size_t)l*DD, ln2_b + (size_t)l*DD, h);
        k_gemm<<<gFF, 256>>>(h, f1w, f1b, nullptr, ff, MM, FFD, DD, 1);  // quickGELU
        k_gemm<<<gD, 256>>>(ff, f2w, f2b, x, x, MM, DD, FFD, 0);         // +residual

        // MoD top-k block: x = where(mask, x, x) == identity -> skipped entirely
    }
    (void)in_sizes; (void)n_in; (void)out_size;
}

// round 4
// speedup vs baseline: 2.6308x; 2.6308x over previous
#include <cuda_runtime.h>
#include <math.h>

// Problem constants
#define BB   16
#define SS   257
#define DD   1024
#define HH   16
#define DHH  64
#define FFD  4096
#define LLN  6
#define PPP  14
#define NPS  16
#define NP   256
#define KC   (3*14*14)   // 588 im2col K
#define MM   (BB*SS)     // 4112 rows
#define LNEPS 1e-5f

// ---------------- scratch ----------------------------------------------------
__device__ float g_col [BB*NP*KC];
__device__ float g_feat[BB*NP*DD];
__device__ float g_h   [MM*DD];
__device__ float g_q   [MM*DD];
__device__ float g_k   [MM*DD];
__device__ float g_v   [MM*DD];
__device__ float g_ctx [MM*DD];
__device__ float g_att [(size_t)BB*HH*SS*SS];
__device__ float g_ff  [(size_t)MM*FFD];

// ---------------- im2col -----------------------------------------------------
__global__ void k_im2col(const float* __restrict__ px) {
    int idx = blockIdx.x * blockDim.x + threadIdx.x;
    const int total = BB*NP*KC;
    if (idx >= total) return;
    int kc = idx % KC;  int bp = idx / KC;
    int p  = bp % NP;   int b  = bp / NP;
    int c  = kc / (PPP*PPP); int rem = kc % (PPP*PPP);
    int i  = rem / PPP, j = rem % PPP;
    int py = p / NPS,   pxi = p % NPS;
    int row = py*PPP + i, col = pxi*PPP + j;
    g_col[idx] = px[((size_t)(b*3 + c)*224 + row)*224 + col];
}

// ---------------- SIMT GEMM (kept only for the conv patch-embed, K=588) -----
#define TBM 64
#define TBN 64
#define TBK 16
__global__ void k_gemm(const float* __restrict__ A, const float* __restrict__ B,
                       const float* __restrict__ bias, const float* __restrict__ add,
                       float* __restrict__ C, int M, int N, int K, int act) {
    __shared__ float As[TBK][TBM+4];
    __shared__ float Bs[TBK][TBN+4];
    int tid = threadIdx.x;
    int tx = tid & 15, ty = tid >> 4;
    int bm = blockIdx.y * TBM, bn = blockIdx.x * TBN;
    int lr = tid >> 2;
    int lc = (tid & 3) * 4;
    float acc[4][4] = {};

    for (int k0 = 0; k0 < K; k0 += TBK) {
        {
            int ar = bm + lr;
            if (ar < M && (k0 + lc + 3) < K) {
                float4 t = *reinterpret_cast<const float4*>(&A[(size_t)ar*K + k0 + lc]);
                As[lc+0][lr] = t.x; As[lc+1][lr] = t.y;
                As[lc+2][lr] = t.z; As[lc+3][lr] = t.w;
            } else {
                #pragma unroll
                for (int i = 0; i < 4; i++) {
                    int kk = k0 + lc + i;
                    As[lc+i][lr] = (ar < M && kk < K) ? A[(size_t)ar*K + kk] : 0.f;
                }
            }
        }
        {
            int br = bn + lr;
            if (br < N && (k0 + lc + 3) < K) {
                float4 t = *reinterpret_cast<const float4*>(&B[(size_t)br*K + k0 + lc]);
                Bs[lc+0][lr] = t.x; Bs[lc+1][lr] = t.y;
                Bs[lc+2][lr] = t.z; Bs[lc+3][lr] = t.w;
            } else {
                #pragma unroll
                for (int i = 0; i < 4; i++) {
                    int kk = k0 + lc + i;
                    Bs[lc+i][lr] = (br < N && kk < K) ? B[(size_t)br*K + kk] : 0.f;
                }
            }
        }
        __syncthreads();
        #pragma unroll
        for (int kk = 0; kk < TBK; kk++) {
            float a[4], b[4];
            #pragma unroll
            for (int i = 0; i < 4; i++) a[i] = As[kk][ty*4+i];
            #pragma unroll
            for (int j = 0; j < 4; j++) b[j] = Bs[kk][tx*4+j];
            #pragma unroll
            for (int i = 0; i < 4; i++)
                #pragma unroll
                for (int j = 0; j < 4; j++)
                    acc[i][j] += a[i] * b[j];
        }
        __syncthreads();
    }

    #pragma unroll
    for (int i = 0; i < 4; i++) {
        int r = bm + ty*4 + i;
        if (r >= M) continue;
        #pragma unroll
        for (int j = 0; j < 4; j++) {
            int c = bn + tx*4 + j;
            if (c >= N) continue;
            float v = acc[i][j];
            if (bias) v += bias[c];
            if (act == 1) v = v / (1.f + __expf(-1.702f * v));
            if (add) v += add[(size_t)r*N + c];
            C[(size_t)r*N + c] = v;
        }
    }
}

// ---------------- tf32 tensor-core GEMM: C = A[M,K] * B[N,K]^T ---------------
// CTA 128x128, BK=16, 8 warps (2x4), warp tile 64x32 of m16n8k8 tf32 MMAs.
// XOR-swizzled smem, cp.async double buffering.
#define PBM 128
#define PBN 128
#define PBK 16

__device__ __forceinline__ unsigned f2tf(float x) {
    unsigned r;
    asm("cvt.rna.tf32.f32 %0, %1;" : "=r"(r) : "f"(x));
    return r;
}

__device__ __forceinline__ void cp_async16(void* smem, const void* gsrc, int bytes) {
    unsigned s = (unsigned)__cvta_generic_to_shared(smem);
    asm volatile("cp.async.cg.shared.global [%0], [%1], 16, %2;" :: "r"(s), "l"(gsrc), "r"(bytes));
}

__device__ __forceinline__ void mma_tf32(float c[4], const unsigned a[4], const unsigned b[2]) {
    asm volatile(
        "mma.sync.aligned.m16n8k8.row.col.f32.tf32.tf32.f32 "
        "{%0,%1,%2,%3}, {%4,%5,%6,%7}, {%8,%9}, {%0,%1,%2,%3};"
        : "+f"(c[0]), "+f"(c[1]), "+f"(c[2]), "+f"(c[3])
        : "r"(a[0]), "r"(a[1]), "r"(a[2]), "r"(a[3]), "r"(b[0]), "r"(b[1]));
}

__global__ void k_mma(const float* __restrict__ A, const float* __restrict__ B,
                      const float* __restrict__ bias, const float* __restrict__ add,
                      float* __restrict__ C, int M, int N, int K, int act) {
    __shared__ float sA[2][PBM*PBK];
    __shared__ float sB[2][PBN*PBK];
    int tid  = threadIdx.x;
    int lane = tid & 31, wid = tid >> 5;
    int wm = wid >> 2, wn = wid & 3;        // 2 x 4 warp grid
    int lg = lane >> 2, lt = lane & 3;      // quad group / thread-in-group
    int bm = blockIdx.y * PBM, bn = blockIdx.x * PBN;

    float c[4][4][4];
    #pragma unroll
    for (int i = 0; i < 4; i++)
        #pragma unroll
        for (int j = 0; j < 4; j++)
            #pragma unroll
            for (int r = 0; r < 4; r++) c[i][j][r] = 0.f;

    const int NIT = K / PBK;

    // stage loaders: 512 float4 chunks per tile, 2 per thread
    auto loadA = [&](int st, int k0) {
        #pragma unroll
        for (int t = 0; t < 2; t++) {
            int slot = tid + t*256;
            int r = slot >> 2, kc = slot & 3;
            int gr = bm + r;
            const float* src = A + (size_t)(gr < M ? gr : 0)*K + k0 + kc*4;
            int bytes = (gr < M) ? 16 : 0;
            float* dst = &sA[st][r*16 + ((kc ^ ((r>>1)&3)) << 2)];
            cp_async16(dst, src, bytes);
        }
    };
    auto loadB = [&](int st, int k0) {
        #pragma unroll
        for (int t = 0; t < 2; t++) {
            int slot = tid + t*256;
            int r = slot >> 2, kc = slot & 3;
            int gr = bn + r;   // always < N (N % 128 == 0)
            const float* src = B + (size_t)gr*K + k0 + kc*4;
            float* dst = &sB[st][r*16 + ((kc ^ ((r>>1)&3)) << 2)];
            cp_async16(dst, src, 16);
        }
    };

    loadA(0, 0); loadB(0, 0);
    asm volatile("cp.async.commit_group;");

    for (int it = 0; it < NIT; it++) {
        int cur = it & 1;
        if (it + 1 < NIT) {
            loadA(cur ^ 1, (it+1)*PBK);
            loadB(cur ^ 1, (it+1)*PBK);
            asm volatile("cp.async.commit_group;");
            asm volatile("cp.async.wait_group 1;");
        } else {
            asm volatile("cp.async.wait_group 0;");
        }
        __syncthreads();

        const float* As = sA[cur];
        const float* Bs = sB[cur];
        #pragma unroll
        for (int ks = 0; ks < 2; ks++) {
            unsigned a[4][4], b[4][2];
            #pragma unroll
            for (int mt = 0; mt < 4; mt++) {
                int m0 = wm*64 + mt*16 + lg;
                int m1 = m0 + 8;
                int ch = 2*ks;
                a[mt][0] = f2tf(As[m0*16 + (( ch    ^ ((m0>>1)&3)) << 2) + lt]);
                a[mt][1] = f2tf(As[m1*16 + (( ch    ^ ((m1>>1)&3)) << 2) + lt]);
                a[mt][2] = f2tf(As[m0*16 + (((ch+1) ^ ((m0>>1)&3)) << 2) + lt]);
                a[mt][3] = f2tf(As[m1*16 + (((ch+1) ^ ((m1>>1)&3)) << 2) + lt]);
            }
            #pragma unroll
            for (int nt = 0; nt < 4; nt++) {
                int n0 = wn*32 + nt*8 + lg;
                int ch = 2*ks;
                b[nt][0] = f2tf(Bs[n0*16 + (( ch    ^ ((n0>>1)&3)) << 2) + lt]);
                b[nt][1] = f2tf(Bs[n0*16 + (((ch+1) ^ ((n0>>1)&3)) << 2) + lt]);
            }
            #pragma unroll
            for (int mt = 0; mt < 4; mt++)
                #pragma unroll
                for (int nt = 0; nt < 4; nt++)
                    mma_tf32(c[mt][nt], a[mt], b[nt]);
        }
        __syncthreads();
    }

    // epilogue: bias -> act -> residual add -> store (float2)
    #pragma unroll
    for (int nt = 0; nt < 4; nt++) {
        int cn = bn + wn*32 + nt*8 + lt*2;
        float bb0 = 0.f, bb1 = 0.f;
        if (bias) { bb0 = bias[cn]; bb1 = bias[cn+1]; }
        #pragma unroll
        for (int mt = 0; mt < 4; mt++) {
            #pragma unroll
            for (int h = 0; h < 2; h++) {
                int r = bm + wm*64 + mt*16 + lg + 8*h;
                if (r < M) {
                    float v0 = c[mt][nt][2*h+0] + bb0;
                    float v1 = c[mt][nt][2*h+1] + bb1;
                    if (act == 1) {
                        v0 = v0 / (1.f + __expf(-1.702f * v0));
                        v1 = v1 / (1.f + __expf(-1.702f * v1));
                    }
                    if (add) {
                        float2 t = *reinterpret_cast<const float2*>(&add[(size_t)r*N + cn]);
                        v0 += t.x; v1 += t.y;
                    }
                    *reinterpret_cast<float2*>(&C[(size_t)r*N + cn]) = make_float2(v0, v1);
                }
            }
        }
    }
}

// ---------------- assemble embeddings ----------------------------------------
__global__ void k_assemble(const float* __restrict__ cls,
                           const float* __restrict__ pos,
                           float* __restrict__ x) {
    int idx = blockIdx.x * blockDim.x + threadIdx.x;
    if (idx >= MM*DD) return;
    int d = idx % DD; int bs = idx / DD;
    int s = bs % SS;  int b = bs / SS;
    float v = (s == 0) ? cls[d] : g_feat[((size_t)(b*NP + s - 1))*DD + d];
    x[idx] = v + pos[(size_t)s*DD + d];
}

// ---------------- LayerNorm ---------------------------------------------------
__global__ void k_ln(const float* __restrict__ x, const float* __restrict__ w,
                     const float* __restrict__ b, float* __restrict__ out) {
    int row = blockIdx.x;
    const float* xr = x + (size_t)row*DD;
    __shared__ float red[256];
    int t = threadIdx.x;
    float s = 0.f;
    for (int i = t; i < DD; i += 256) s += xr[i];
    red[t] = s; __syncthreads();
    for (int st = 128; st > 0; st >>= 1) { if (t < st) red[t] += red[t+st]; __syncthreads(); }
    float mean = red[0] * (1.f/DD);
    __syncthreads();
    float vs = 0.f;
    for (int i = t; i < DD; i += 256) { float d = xr[i]-mean; vs += d*d; }
    red[t] = vs; __syncthreads();
    for (int st = 128; st > 0; st >>= 1) { if (t < st) red[t] += red[t+st]; __syncthreads(); }
    float rstd = rsqrtf(red[0] * (1.f/DD) + LNEPS);
    float* o = out + (size_t)row*DD;
    for (int i = t; i < DD; i += 256) o[i] = (xr[i]-mean)*rstd*w[i] + b[i];
}

// ---------------- attention scores -------------------------------------------
__global__ void k_scores(const float* __restrict__ Q, const float* __restrict__ Kt) {
    int bh = blockIdx.z;
    int b = bh / HH, h = bh % HH;
    int q0 = blockIdx.y * 16, k0 = blockIdx.x * 16;
    __shared__ float Qs[16][DHH+1];
    __shared__ float Ks[16][DHH+1];
    int tid = threadIdx.y*16 + threadIdx.x;
    int lr = tid >> 4;
    int lc = (tid & 15) * 4;
    {
        int qr = q0 + lr;
        if (qr < SS) {
            float4 t = *reinterpret_cast<const float4*>(&Q[((size_t)(b*SS+qr))*DD + h*DHH + lc]);
            Qs[lr][lc]=t.x; Qs[lr][lc+1]=t.y; Qs[lr][lc+2]=t.z; Qs[lr][lc+3]=t.w;
        } else { Qs[lr][lc]=Qs[lr][lc+1]=Qs[lr][lc+2]=Qs[lr][lc+3]=0.f; }
        int kr = k0 + lr;
        if (kr < SS) {
            float4 t = *reinterpret_cast<const float4*>(&Kt[((size_t)(b*SS+kr))*DD + h*DHH + lc]);
            Ks[lr][lc]=t.x; Ks[lr][lc+1]=t.y; Ks[lr][lc+2]=t.z; Ks[lr][lc+3]=t.w;
        } else { Ks[lr][lc]=Ks[lr][lc+1]=Ks[lr][lc+2]=Ks[lr][lc+3]=0.f; }
    }
    __syncthreads();
    int q = q0 + threadIdx.y, k = k0 + threadIdx.x;
    if (q < SS && k < SS) {
        float acc = 0.f;
        #pragma unroll
        for (int d = 0; d < DHH; d++) acc += Qs[threadIdx.y][d] * Ks[threadIdx.x][d];
        g_att[((size_t)bh*SS + q)*SS + k] = acc * 0.125f;
    }
}

// ---------------- softmax -----------------------------------------------------
__global__ void k_softmax() {
    size_t row = blockIdx.x;
    float* p = g_att + row * (size_t)SS;
    int t = threadIdx.x;
    float a = p[t];
    float extra = (t == 0) ? p[256] : -1e30f;
    __shared__ float red[256];
    float m = fmaxf(a, extra);
    red[t] = m; __syncthreads();
    for (int st = 128; st > 0; st >>= 1) { if (t < st) red[t] = fmaxf(red[t], red[t+st]); __syncthreads(); }
    m = red[0];
    __syncthreads();
    float ea = __expf(a - m);
    float eb = (t == 0) ? __expf(extra - m) : 0.f;
    red[t] = ea + eb; __syncthreads();
    for (int st = 128; st > 0; st >>= 1) { if (t < st) red[t] += red[t+st]; __syncthreads(); }
    float inv = 1.f / red[0];
    p[t] = ea * inv;
    if (t == 0) p[256] = eb * inv;
}

// ---------------- ctx = attn @ V ----------------------------------------------
__global__ void k_ctx(const float* __restrict__ V, float* __restrict__ Ctx) {
    int bh = blockIdx.y; int b = bh / HH, h = bh % HH;
    int q0 = blockIdx.x * 16;
    int tx = threadIdx.x, ty = threadIdx.y;
    int tid = ty*16 + tx;
    __shared__ float As[16][17];
    __shared__ float Vs[16][DHH];
    const float* att = g_att + (size_t)bh*SS*SS;
    float acc[4] = {0.f, 0.f, 0.f, 0.f};
    int vlr = tid >> 4, vlc = (tid & 15) * 4;
    for (int k0 = 0; k0 < SS; k0 += 16) {
        int q = q0 + ty, kk_ = k0 + tx;
        As[ty][tx] = (q < SS && kk_ < SS) ? att[(size_t)q*SS + kk_] : 0.f;
        int kv = k0 + vlr;
        if (kv < SS) {
            float4 t4 = *reinterpret_cast<const float4*>(&V[((size_t)(b*SS+kv))*DD + h*DHH + vlc]);
            Vs[vlr][vlc]=t4.x; Vs[vlr][vlc+1]=t4.y; Vs[vlr][vlc+2]=t4.z; Vs[vlr][vlc+3]=t4.w;
        } else {
            Vs[vlr][vlc]=Vs[vlr][vlc+1]=Vs[vlr][vlc+2]=Vs[vlr][vlc+3]=0.f;
        }
        __syncthreads();
        #pragma unroll
        for (int kk = 0; kk < 16; kk++) {
            float a = As[ty][kk];
            #pragma unroll
            for (int j = 0; j < 4; j++) acc[j] += a * Vs[kk][tx + 16*j];
        }
        __syncthreads();
    }
    int q = q0 + ty;
    if (q < SS) {
        size_t base = ((size_t)(b*SS+q))*DD + h*DHH;
        #pragma unroll
        for (int j = 0; j < 4; j++) Ctx[base + tx + 16*j] = acc[j];
    }
}

// ---------------- host orchestration ------------------------------------------
extern "C" void kernel_launch(void* const* d_in, const int* in_sizes, int n_in,
                              void* d_out, int out_size) {
    const float* pixel    = (const float*)d_in[0];
    const float* patch_w  = (const float*)d_in[1];
    const float* class_e  = (const float*)d_in[2];
    const float* pos_e    = (const float*)d_in[3];
    const float* ln1_w    = (const float*)d_in[4];
    const float* ln1_b    = (const float*)d_in[5];
    const float* q_w      = (const float*)d_in[6];
    const float* q_b      = (const float*)d_in[7];
    const float* k_w      = (const float*)d_in[8];
    const float* k_b      = (const float*)d_in[9];
    const float* v_w      = (const float*)d_in[10];
    const float* v_b      = (const float*)d_in[11];
    const float* o_w      = (const float*)d_in[12];
    const float* o_b      = (const float*)d_in[13];
    const float* ln2_w    = (const float*)d_in[14];
    const float* ln2_b    = (const float*)d_in[15];
    const float* fc1_w    = (const float*)d_in[16];
    const float* fc1_b    = (const float*)d_in[17];
    const float* fc2_w    = (const float*)d_in[18];
    const float* fc2_b    = (const float*)d_in[19];
    float* x = (float*)d_out;

    float *col, *feat, *h, *q, *k, *v, *ctx, *ff;
    cudaGetSymbolAddress((void**)&col,  g_col);
    cudaGetSymbolAddress((void**)&feat, g_feat);
    cudaGetSymbolAddress((void**)&h,    g_h);
    cudaGetSymbolAddress((void**)&q,    g_q);
    cudaGetSymbolAddress((void**)&k,    g_k);
    cudaGetSymbolAddress((void**)&v,    g_v);
    cudaGetSymbolAddress((void**)&ctx,  g_ctx);
    cudaGetSymbolAddress((void**)&ff,   g_ff);

    // --- embeddings ---
    k_im2col<<<(BB*NP*KC + 255)/256, 256>>>(pixel);
    k_gemm<<<dim3(DD/TBN, (BB*NP + TBM-1)/TBM), 256>>>(col, patch_w, nullptr, nullptr,
                                                       feat, BB*NP, DD, KC, 0);
    k_assemble<<<(MM*DD + 255)/256, 256>>>(class_e, pos_e, x);

    dim3 gD (DD/PBN,  (MM + PBM-1)/PBM);    // (8, 33)
    dim3 gFF(FFD/PBN, (MM + PBM-1)/PBM);    // (32, 33)

    for (int l = 0; l < LLN; l++) {
        const float* qw = q_w + (size_t)l*DD*DD;  const float* qb = q_b + (size_t)l*DD;
        const float* kw = k_w + (size_t)l*DD*DD;  const float* kb = k_b + (size_t)l*DD;
        const float* vw = v_w + (size_t)l*DD*DD;  const float* vb = v_b + (size_t)l*DD;
        const float* ow = o_w + (size_t)l*DD*DD;  const float* ob = o_b + (size_t)l*DD;
        const float* f1w = fc1_w + (size_t)l*FFD*DD; const float* f1b = fc1_b + (size_t)l*FFD;
        const float* f2w = fc2_w + (size_t)l*DD*FFD; const float* f2b = fc2_b + (size_t)l*DD;

        // attention block
        k_ln<<<MM, 256>>>(x, ln1_w + (size_t)l*DD, ln1_b + (size_t)l*DD, h);
        k_mma<<<gD, 256>>>(h, qw, qb, nullptr, q, MM, DD, DD, 0);
        k_mma<<<gD, 256>>>(h, kw, kb, nullptr, k, MM, DD, DD, 0);
        k_mma<<<gD, 256>>>(h, vw, vb, nullptr, v, MM, DD, DD, 0);
        k_scores<<<dim3(17, 17, BB*HH), dim3(16,16)>>>(q, k);
        k_softmax<<<BB*HH*SS, 256>>>();
        k_ctx<<<dim3(17, BB*HH), dim3(16,16)>>>(v, ctx);
        k_mma<<<gD, 256>>>(ctx, ow, ob, x, x, MM, DD, DD, 0);    // +residual

        // MLP block
        k_ln<<<MM, 256>>>(x, ln2_w + (size_t)l*DD, ln2_b + (size_t)l*DD, h);
        k_mma<<<gFF, 256>>>(h, f1w, f1b, nullptr, ff, MM, FFD, DD, 1);   // quickGELU
        k_mma<<<gD, 256>>>(ff, f2w, f2b, x, x, MM, DD, FFD, 0);          // +residual

        // MoD top-k block: identity -> skipped
    }
    (void)in_sizes; (void)n_in; (void)out_size;
}